// round 8
// baseline (speedup 1.0000x reference)
#include <cuda_runtime.h>
#include <cuda.h>
#include <math.h>
#include <stdint.h>

// ConfidenceCalibration: softmax over bins sums to 1 =>
//   final = clip(sigmoid(mean(x,-1)) * bin_scaling[bucketize(base)], 0, 1)
// Pure HBM read of x (128 MB) + tiny epilogue.
//
// R5 -> R6: LDG-based kernels plateau at ~5.5TB/s (68.7-70.4% DRAM) across
// all grid shapes => request-shape experiment: cp.async.bulk (UBLKCP) 32KB
// stage transfers into smem, 4-stage mbarrier pipeline, 1 CTA/SM, reduce
// rows from smem. Controller sees 148 large in-order streams instead of
// ~8000 interleaved 512B LDG requests.

#define STAGES 4
#define ROWS_PER_STAGE 8
#define ROW_BYTES 4096              // D=1024 floats
#define STAGE_BYTES (ROWS_PER_STAGE * ROW_BYTES)   // 32768
#define DATA_OFF 1024               // barriers live below this
#define SMEM_TOTAL (DATA_OFF + STAGES * STAGE_BYTES)

__device__ __forceinline__ uint32_t smem_u32(const void* p) {
    uint32_t a;
    asm("{ .reg .u64 t; cvta.to.shared.u64 t, %1; cvt.u32.u64 %0, t; }"
        : "=r"(a) : "l"(p));
    return a;
}

__device__ __forceinline__ void mbar_init(uint32_t bar, uint32_t cnt) {
    asm volatile("mbarrier.init.shared.b64 [%0], %1;" :: "r"(bar), "r"(cnt) : "memory");
}
__device__ __forceinline__ void mbar_expect_tx(uint32_t bar, uint32_t bytes) {
    asm volatile("mbarrier.arrive.expect_tx.shared.b64 _, [%0], %1;"
                 :: "r"(bar), "r"(bytes) : "memory");
}
__device__ __forceinline__ void mbar_arrive(uint32_t bar) {
    asm volatile("mbarrier.arrive.shared.b64 _, [%0];" :: "r"(bar) : "memory");
}
__device__ __forceinline__ void mbar_wait(uint32_t bar, uint32_t parity) {
    uint32_t done;
    asm volatile(
        "{\n\t.reg .pred p;\n\t"
        "mbarrier.try_wait.parity.acquire.cta.shared::cta.b64 p, [%1], %2;\n\t"
        "selp.b32 %0, 1, 0, p;\n\t}"
        : "=r"(done) : "r"(bar), "r"(parity) : "memory");
    if (!done) {
        asm volatile(
            "{\n\t.reg .pred P1;\n\t"
            "W_%=:\n\t"
            "mbarrier.try_wait.parity.acquire.cta.shared::cta.b64 P1, [%0], %1, 0x989680;\n\t"
            "@P1 bra.uni D_%=;\n\t"
            "bra.uni W_%=;\n\t"
            "D_%=:\n\t}"
            :: "r"(bar), "r"(parity) : "memory");
    }
}
__device__ __forceinline__ void bulk_g2s(uint32_t dst, const void* src,
                                         uint32_t bytes, uint32_t bar) {
    asm volatile(
        "cp.async.bulk.shared::cta.global.mbarrier::complete_tx::bytes "
        "[%0], [%1], %2, [%3];"
        :: "r"(dst), "l"(src), "r"(bytes), "r"(bar) : "memory");
}

__device__ __forceinline__ float warp_reduce_sum(float s) {
    #pragma unroll
    for (int o = 16; o; o >>= 1) s += __shfl_xor_sync(0xffffffffu, s, o);
    return s;
}

__device__ __forceinline__ void finalize(float s, float invD, int NB,
                                         const float* __restrict__ bin_scaling,
                                         float* __restrict__ out, int row) {
    float mean = s * invD;
    float base = 1.0f / (1.0f + expf(-mean));
    // searchsorted(linspace(0,1,NB+1), base, 'right') - 1
    int idx = -1;
    for (int i = 0; i <= NB; i++) {
        float bnd = (float)i / (float)NB;
        if (bnd <= base) idx = i; else break;
    }
    float scale = (idx >= 0 && idx < NB) ? bin_scaling[idx] : 0.0f;
    out[row] = fminf(fmaxf(base * scale, 0.0f), 1.0f);
}

// D == 1024, B % 8 == 0. 288 threads: warps 0-7 consume, warp 8 produces.
__global__ void __launch_bounds__(288, 1) confcal_tma_1024(
        const float* __restrict__ x,
        const float* __restrict__ bin_scaling,
        float* __restrict__ out,
        int n_chunks, int NB) {
    extern __shared__ __align__(128) unsigned char smem_raw[];
    const uint32_t sbase = smem_u32(smem_raw);
    const int tid  = threadIdx.x;
    const int warp = tid >> 5;
    const int lane = tid & 31;
    const int gsz  = gridDim.x;

    // barriers: full[s] at sbase + s*16, empty[s] at sbase + s*16 + 8
    if (tid == 0) {
        #pragma unroll
        for (int s = 0; s < STAGES; s++) {
            mbar_init(sbase + s * 16, 1);        // full: 1 expect_tx arrival
            mbar_init(sbase + s * 16 + 8, 8);    // empty: 8 consumer warps
        }
    }
    __syncthreads();

    if (warp == 8) {
        // Producer: one elected thread issues all stage loads with backpressure.
        if (lane == 0) {
            int stage = 0, phase = 1;            // first empty-wait passes
            for (int c = blockIdx.x; c < n_chunks; c += gsz) {
                uint32_t full_b  = sbase + stage * 16;
                uint32_t empty_b = full_b + 8;
                mbar_wait(empty_b, phase);
                mbar_expect_tx(full_b, STAGE_BYTES);
                bulk_g2s(sbase + DATA_OFF + stage * STAGE_BYTES,
                         x + (size_t)c * (ROWS_PER_STAGE * 1024),
                         STAGE_BYTES, full_b);
                if (++stage == STAGES) { stage = 0; phase ^= 1; }
            }
        }
    } else {
        // Consumers: warp w reduces row w of each arriving stage.
        int stage = 0, phase = 0;
        const float4* sdata = reinterpret_cast<const float4*>(smem_raw + DATA_OFF);
        for (int c = blockIdx.x; c < n_chunks; c += gsz) {
            uint32_t full_b  = sbase + stage * 16;
            uint32_t empty_b = full_b + 8;
            mbar_wait(full_b, phase);

            const float4* rp = sdata + (size_t)stage * (STAGE_BYTES / 16)
                                     + warp * (ROW_BYTES / 16) + lane;
            float4 v0 = rp[0 * 32];
            float4 v1 = rp[1 * 32];
            float4 v2 = rp[2 * 32];
            float4 v3 = rp[3 * 32];
            float4 v4 = rp[4 * 32];
            float4 v5 = rp[5 * 32];
            float4 v6 = rp[6 * 32];
            float4 v7 = rp[7 * 32];
            float a0 = (v0.x + v0.y) + (v0.z + v0.w);
            float a1 = (v1.x + v1.y) + (v1.z + v1.w);
            float a2 = (v2.x + v2.y) + (v2.z + v2.w);
            float a3 = (v3.x + v3.y) + (v3.z + v3.w);
            float a4 = (v4.x + v4.y) + (v4.z + v4.w);
            float a5 = (v5.x + v5.y) + (v5.z + v5.w);
            float a6 = (v6.x + v6.y) + (v6.z + v6.w);
            float a7 = (v7.x + v7.y) + (v7.z + v7.w);
            float s = ((a0 + a1) + (a2 + a3)) + ((a4 + a5) + (a6 + a7));

            s = warp_reduce_sum(s);   // shuffles also fence: all lanes done reading
            if (lane == 0) {
                finalize(s, 1.0f / 1024.0f, NB, bin_scaling, out,
                         c * ROWS_PER_STAGE + warp);
                mbar_arrive(empty_b);
            }
            if (++stage == STAGES) { stage = 0; phase ^= 1; }
        }
    }
}

// Generic fallback (any D): best-known LDG kernel (R2 shape).
__global__ void confcal_gen(const float* __restrict__ x,
                            const float* __restrict__ bin_scaling,
                            float* __restrict__ out,
                            int B, int D, int NB) {
    const int gwarp = (blockIdx.x * blockDim.x + threadIdx.x) >> 5;
    const int lane  = threadIdx.x & 31;
    if (gwarp >= B) return;

    const float* rowp = x + (size_t)gwarp * (size_t)D;
    const int nvec = D >> 2;
    const float4* row4 = reinterpret_cast<const float4*>(rowp);

    float s = 0.0f;
    #pragma unroll 8
    for (int i = lane; i < nvec; i += 32) {
        float4 v = __ldcs(row4 + i);
        s += (v.x + v.y) + (v.z + v.w);
    }
    for (int i = (nvec << 2) + lane; i < D; i += 32) s += rowp[i];

    s = warp_reduce_sum(s);
    if (lane == 0) finalize(s, 1.0f / (float)D, NB, bin_scaling, out, gwarp);
}

extern "C" void kernel_launch(void* const* d_in, const int* in_sizes, int n_in,
                              void* d_out, int out_size) {
    const float* x           = (const float*)d_in[0];
    const float* bin_scaling = (const float*)d_in[7];
    float* out = (float*)d_out;

    const int B  = out_size;            // 32768
    const int D  = in_sizes[0] / B;     // 1024
    const int NB = in_sizes[7];         // 15

    if (D == 1024 && (B % ROWS_PER_STAGE) == 0 && (((uintptr_t)x) & 15u) == 0) {
        int nsm = 148;
        cudaDeviceGetAttribute(&nsm, cudaDevAttrMultiProcessorCount, 0);
        static int smem_set = 0;
        if (!smem_set) {
            cudaFuncSetAttribute(confcal_tma_1024,
                                 cudaFuncAttributeMaxDynamicSharedMemorySize,
                                 SMEM_TOTAL);
            smem_set = 1;
        }
        const int n_chunks = B / ROWS_PER_STAGE;   // 4096
        confcal_tma_1024<<<nsm, 288, SMEM_TOTAL>>>(x, bin_scaling, out,
                                                   n_chunks, NB);
    } else {
        const int threads = 256;
        const int blocks  = (B * 32 + threads - 1) / threads;
        confcal_gen<<<blocks, threads>>>(x, bin_scaling, out, B, D, NB);
    }
}

// round 9
// speedup vs baseline: 1.3497x; 1.3497x over previous
#include <cuda_runtime.h>
#include <math.h>
#include <stdint.h>

// ConfidenceCalibration: softmax over bins sums to 1 =>
//   final = clip(sigmoid(mean(x,-1)) * bin_scaling[bucketize(base)], 0, 1)
// Pure HBM read of x (128 MB) + tiny epilogue.
//
// R8 -> R9: back to the best LDG shape (R2: one row per warp, one-shot
// CTAs, front-batched 8x LDG.128). New lever: .L2::256B prefetch-size hint
// on the loads — halves L2->DRAM request count (256B fetch per sector miss
// instead of 4x32B), targeting DRAM burst/page efficiency. TMA staging
// experiment (R8) regressed to 50% DRAM and is abandoned.

__device__ __forceinline__ float4 ldg_nc_256(const float4* p) {
    float4 v;
    asm volatile("ld.global.nc.L2::256B.v4.f32 {%0,%1,%2,%3}, [%4];"
                 : "=f"(v.x), "=f"(v.y), "=f"(v.z), "=f"(v.w)
                 : "l"(p));
    return v;
}

__device__ __forceinline__ float warp_reduce_sum(float s) {
    #pragma unroll
    for (int o = 16; o; o >>= 1) s += __shfl_xor_sync(0xffffffffu, s, o);
    return s;
}

__device__ __forceinline__ void finalize(float s, float invD, int NB,
                                         const float* __restrict__ bin_scaling,
                                         float* __restrict__ out, int row) {
    float mean = s * invD;
    float base = 1.0f / (1.0f + expf(-mean));
    // searchsorted(linspace(0,1,NB+1), base, 'right') - 1
    int idx = -1;
    for (int i = 0; i <= NB; i++) {
        float bnd = (float)i / (float)NB;
        if (bnd <= base) idx = i; else break;
    }
    float scale = (idx >= 0 && idx < NB) ? bin_scaling[idx] : 0.0f;
    out[row] = fminf(fmaxf(base * scale, 0.0f), 1.0f);
}

// Specialized: D == 1024. One row per warp, 8x LDG.128 front-batched.
__global__ void __launch_bounds__(256) confcal_kernel_1024(
        const float* __restrict__ x,
        const float* __restrict__ bin_scaling,
        float* __restrict__ out,
        int B, int NB) {
    const int gwarp = (blockIdx.x * blockDim.x + threadIdx.x) >> 5;
    const int lane  = threadIdx.x & 31;
    if (gwarp >= B) return;

    const float4* p = reinterpret_cast<const float4*>(x + (size_t)gwarp * 1024u) + lane;

    // 8 independent loads, all in flight before arithmetic. 256B L2 fetch hint.
    float4 v0 = ldg_nc_256(p + 0 * 32);
    float4 v1 = ldg_nc_256(p + 1 * 32);
    float4 v2 = ldg_nc_256(p + 2 * 32);
    float4 v3 = ldg_nc_256(p + 3 * 32);
    float4 v4 = ldg_nc_256(p + 4 * 32);
    float4 v5 = ldg_nc_256(p + 5 * 32);
    float4 v6 = ldg_nc_256(p + 6 * 32);
    float4 v7 = ldg_nc_256(p + 7 * 32);

    float a0 = (v0.x + v0.y) + (v0.z + v0.w);
    float a1 = (v1.x + v1.y) + (v1.z + v1.w);
    float a2 = (v2.x + v2.y) + (v2.z + v2.w);
    float a3 = (v3.x + v3.y) + (v3.z + v3.w);
    float a4 = (v4.x + v4.y) + (v4.z + v4.w);
    float a5 = (v5.x + v5.y) + (v5.z + v5.w);
    float a6 = (v6.x + v6.y) + (v6.z + v6.w);
    float a7 = (v7.x + v7.y) + (v7.z + v7.w);
    float s = ((a0 + a1) + (a2 + a3)) + ((a4 + a5) + (a6 + a7));

    s = warp_reduce_sum(s);
    if (lane == 0) finalize(s, 1.0f / 1024.0f, NB, bin_scaling, out, gwarp);
}

// Generic fallback for other D
__global__ void confcal_kernel_gen(const float* __restrict__ x,
                                   const float* __restrict__ bin_scaling,
                                   float* __restrict__ out,
                                   int B, int D, int NB) {
    const int gwarp = (blockIdx.x * blockDim.x + threadIdx.x) >> 5;
    const int lane  = threadIdx.x & 31;
    if (gwarp >= B) return;

    const float* rowp = x + (size_t)gwarp * (size_t)D;
    const int nvec = D >> 2;
    const float4* row4 = reinterpret_cast<const float4*>(rowp);

    float s = 0.0f;
    #pragma unroll 8
    for (int i = lane; i < nvec; i += 32) {
        float4 v = __ldcs(row4 + i);
        s += (v.x + v.y) + (v.z + v.w);
    }
    for (int i = (nvec << 2) + lane; i < D; i += 32) s += rowp[i];

    s = warp_reduce_sum(s);
    if (lane == 0) finalize(s, 1.0f / (float)D, NB, bin_scaling, out, gwarp);
}

extern "C" void kernel_launch(void* const* d_in, const int* in_sizes, int n_in,
                              void* d_out, int out_size) {
    const float* x           = (const float*)d_in[0];
    const float* bin_scaling = (const float*)d_in[7];
    float* out = (float*)d_out;

    const int B  = out_size;            // 32768
    const int D  = in_sizes[0] / B;     // 1024
    const int NB = in_sizes[7];         // 15

    const int threads = 256;            // 8 warps = 8 rows per block
    const int rows_per_block = threads / 32;
    const int blocks = (B + rows_per_block - 1) / rows_per_block;

    if (D == 1024 && (((uintptr_t)x) & 15u) == 0) {
        confcal_kernel_1024<<<blocks, threads>>>(x, bin_scaling, out, B, NB);
    } else {
        confcal_kernel_gen<<<blocks, threads>>>(x, bin_scaling, out, B, D, NB);
    }
}

// round 10
// speedup vs baseline: 1.4701x; 1.0892x over previous
#include <cuda_runtime.h>
#include <math.h>
#include <stdint.h>

// ConfidenceCalibration: softmax over bins sums to 1 =>
//   final = clip(sigmoid(mean(x,-1)) * bin_scaling[bucketize(base)], 0, 1)
// Pure HBM read of x (128 MB) + tiny epilogue.
//
// R9 -> R10: all memory-side levers (MLP, grid shape, TMA staging, cache
// policy, L2 fetch-size hint) plateau at 68.7-70.4% DRAM => ~5.5 TB/s is
// the effective streaming ceiling here. Revert to the measured-best R2
// config (front-batched __ldcs, one row/warp, one-shot 256-thr CTAs) and
// halve reduction-tree issue traffic with packed add.rn.f32x2 (PTX-only
// on sm_103a) as a final issue-pressure probe.

__device__ __forceinline__ uint64_t pack_f32x2(float lo, float hi) {
    uint64_t r;
    asm("mov.b64 %0, {%1, %2};" : "=l"(r) : "f"(lo), "f"(hi));
    return r;
}
__device__ __forceinline__ uint64_t add_f32x2(uint64_t a, uint64_t b) {
    uint64_t r;
    asm("add.rn.f32x2 %0, %1, %2;" : "=l"(r) : "l"(a), "l"(b));
    return r;
}
__device__ __forceinline__ float hsum_f32x2(uint64_t a) {
    float lo, hi;
    asm("mov.b64 {%0, %1}, %2;" : "=f"(lo), "=f"(hi) : "l"(a));
    return lo + hi;
}

__device__ __forceinline__ float warp_reduce_sum(float s) {
    #pragma unroll
    for (int o = 16; o; o >>= 1) s += __shfl_xor_sync(0xffffffffu, s, o);
    return s;
}

__device__ __forceinline__ void finalize(float s, float invD, int NB,
                                         const float* __restrict__ bin_scaling,
                                         float* __restrict__ out, int row) {
    float mean = s * invD;
    float base = 1.0f / (1.0f + expf(-mean));
    // searchsorted(linspace(0,1,NB+1), base, 'right') - 1
    int idx = -1;
    for (int i = 0; i <= NB; i++) {
        float bnd = (float)i / (float)NB;
        if (bnd <= base) idx = i; else break;
    }
    float scale = (idx >= 0 && idx < NB) ? bin_scaling[idx] : 0.0f;
    out[row] = fminf(fmaxf(base * scale, 0.0f), 1.0f);
}

// Specialized: D == 1024. One row per warp, 8x LDG.128 front-batched,
// packed f32x2 reduction tree.
__global__ void __launch_bounds__(256) confcal_kernel_1024(
        const float* __restrict__ x,
        const float* __restrict__ bin_scaling,
        float* __restrict__ out,
        int B, int NB) {
    const int gwarp = (blockIdx.x * blockDim.x + threadIdx.x) >> 5;
    const int lane  = threadIdx.x & 31;
    if (gwarp >= B) return;

    const float4* p = reinterpret_cast<const float4*>(x + (size_t)gwarp * 1024u) + lane;

    // 8 independent streaming loads, all in flight before arithmetic.
    float4 v0 = __ldcs(p + 0 * 32);
    float4 v1 = __ldcs(p + 1 * 32);
    float4 v2 = __ldcs(p + 2 * 32);
    float4 v3 = __ldcs(p + 3 * 32);
    float4 v4 = __ldcs(p + 4 * 32);
    float4 v5 = __ldcs(p + 5 * 32);
    float4 v6 = __ldcs(p + 6 * 32);
    float4 v7 = __ldcs(p + 7 * 32);

    // Packed f32x2 pairwise tree: 16 packs, 15 packed adds, 1 scalar add.
    uint64_t p0 = add_f32x2(pack_f32x2(v0.x, v0.y), pack_f32x2(v0.z, v0.w));
    uint64_t p1 = add_f32x2(pack_f32x2(v1.x, v1.y), pack_f32x2(v1.z, v1.w));
    uint64_t p2 = add_f32x2(pack_f32x2(v2.x, v2.y), pack_f32x2(v2.z, v2.w));
    uint64_t p3 = add_f32x2(pack_f32x2(v3.x, v3.y), pack_f32x2(v3.z, v3.w));
    uint64_t p4 = add_f32x2(pack_f32x2(v4.x, v4.y), pack_f32x2(v4.z, v4.w));
    uint64_t p5 = add_f32x2(pack_f32x2(v5.x, v5.y), pack_f32x2(v5.z, v5.w));
    uint64_t p6 = add_f32x2(pack_f32x2(v6.x, v6.y), pack_f32x2(v6.z, v6.w));
    uint64_t p7 = add_f32x2(pack_f32x2(v7.x, v7.y), pack_f32x2(v7.z, v7.w));
    uint64_t q0 = add_f32x2(add_f32x2(p0, p1), add_f32x2(p2, p3));
    uint64_t q1 = add_f32x2(add_f32x2(p4, p5), add_f32x2(p6, p7));
    float s = hsum_f32x2(add_f32x2(q0, q1));

    s = warp_reduce_sum(s);
    if (lane == 0) finalize(s, 1.0f / 1024.0f, NB, bin_scaling, out, gwarp);
}

// Generic fallback for other D
__global__ void confcal_kernel_gen(const float* __restrict__ x,
                                   const float* __restrict__ bin_scaling,
                                   float* __restrict__ out,
                                   int B, int D, int NB) {
    const int gwarp = (blockIdx.x * blockDim.x + threadIdx.x) >> 5;
    const int lane  = threadIdx.x & 31;
    if (gwarp >= B) return;

    const float* rowp = x + (size_t)gwarp * (size_t)D;
    const int nvec = D >> 2;
    const float4* row4 = reinterpret_cast<const float4*>(rowp);

    float s = 0.0f;
    #pragma unroll 8
    for (int i = lane; i < nvec; i += 32) {
        float4 v = __ldcs(row4 + i);
        s += (v.x + v.y) + (v.z + v.w);
    }
    for (int i = (nvec << 2) + lane; i < D; i += 32) s += rowp[i];

    s = warp_reduce_sum(s);
    if (lane == 0) finalize(s, 1.0f / (float)D, NB, bin_scaling, out, gwarp);
}

extern "C" void kernel_launch(void* const* d_in, const int* in_sizes, int n_in,
                              void* d_out, int out_size) {
    const float* x           = (const float*)d_in[0];
    const float* bin_scaling = (const float*)d_in[7];
    float* out = (float*)d_out;

    const int B  = out_size;            // 32768
    const int D  = in_sizes[0] / B;     // 1024
    const int NB = in_sizes[7];         // 15

    const int threads = 256;            // 8 warps = 8 rows per block
    const int rows_per_block = threads / 32;
    const int blocks = (B + rows_per_block - 1) / rows_per_block;

    if (D == 1024 && (((uintptr_t)x) & 15u) == 0) {
        confcal_kernel_1024<<<blocks, threads>>>(x, bin_scaling, out, B, NB);
    } else {
        confcal_kernel_gen<<<blocks, threads>>>(x, bin_scaling, out, B, D, NB);
    }
}